// round 12
// baseline (speedup 1.0000x reference)
#include <cuda_runtime.h>
#include <math.h>
#include <float.h>
#include <stdint.h>

// ---------------- problem constants ----------------
constexpr int Bc  = 4;
constexpr int Sc  = 2048;
constexpr int Dc  = 1024;
constexpr int Hc  = 16;
constexpr int DHc = 64;
constexpr int Ec  = 16;
constexpr int Ic  = 1024;
constexpr int Tc  = Bc * Sc;                 // 8192 tokens
constexpr int PERM_MAX = 2 * Tc + 128 * Ec;  // 18432, multiple of 128

constexpr int LDSS = 36;                          // smem row stride (u32) = 144 B
constexpr uint32_t ROWB = LDSS * 4;               // 144
constexpr uint32_t SSTB = 384 * ROWB;             // 55296 B per stage (128 A + 256 B rows)
constexpr int SMEM_GEMM = 4 * (int)SSTB;          // 221184 B
constexpr uint32_t STAGE_BYTES = 384 * 128;       // 49152 expected tx per stage

// ---------------- scratch (device globals; no allocs allowed) ----------------
__device__ float g_A[Tc * Dc];
__device__ float g_B[Tc * Ic];
__device__ float g_C[Tc * Ic];
__device__ float g_D[Tc * Dc];
__device__ float g_E[Tc * Dc];
__device__ float g_F[Tc * Dc];
__device__ float g_cg[PERM_MAX * Ic];
__device__ float g_cu[PERM_MAX * Ic];

__device__ int   g_cnt[Ec];
__device__ int   g_fill[Ec];
__device__ int   g_pbase[Ec + 1];
__device__ int   g_end[Ec];
__device__ int   g_total;
__device__ int   g_perm[PERM_MAX];
__device__ float g_wgt[PERM_MAX];
__device__ int   g_tok_e[2 * Tc];
__device__ float g_tok_w[2 * Tc];

// ---------------- mma / async helpers ----------------
__device__ __forceinline__ uint32_t f2tf32(float f) {
    uint32_t r;
    asm("cvt.rna.tf32.f32 %0, %1;" : "=r"(r) : "f"(f));
    return r;
}

__device__ __forceinline__ void mma8(float* c, const uint32_t* a, const uint32_t* b) {
    asm volatile(
        "mma.sync.aligned.m16n8k8.row.col.f32.tf32.tf32.f32 "
        "{%0,%1,%2,%3}, {%4,%5,%6,%7}, {%8,%9}, {%0,%1,%2,%3};"
        : "+f"(c[0]), "+f"(c[1]), "+f"(c[2]), "+f"(c[3])
        : "r"(a[0]), "r"(a[1]), "r"(a[2]), "r"(a[3]), "r"(b[0]), "r"(b[1]));
}

__device__ __forceinline__ void ldsm_x4(uint32_t* r, uint32_t addr) {
    asm volatile("ldmatrix.sync.aligned.m8n8.x4.shared.b16 {%0,%1,%2,%3}, [%4];"
        : "=r"(r[0]), "=r"(r[1]), "=r"(r[2]), "=r"(r[3]) : "r"(addr));
}

// one 128-byte row: global -> shared, completion via mbarrier complete_tx
__device__ __forceinline__ void cpbulk(uint32_t dst, const void* src, uint32_t mbar) {
    asm volatile(
        "cp.async.bulk.shared::cluster.global.mbarrier::complete_tx::bytes [%0], [%1], 128, [%2];"
        :: "r"(dst), "l"(src), "r"(mbar) : "memory");
}

#define MBAR_INIT(addr, cnt) \
    asm volatile("mbarrier.init.shared.b64 [%0], %1;" :: "r"(addr), "r"(cnt) : "memory")
#define MBAR_EXPECT(addr, bytes) \
    asm volatile("mbarrier.arrive.expect_tx.shared.b64 _, [%0], %1;" \
                 :: "r"(addr), "r"(bytes) : "memory")
#define MBAR_WAIT(addr, parity) do { \
    uint32_t _mb = (addr); uint32_t _p = (parity); uint32_t _done; \
    asm volatile("{\n\t.reg .pred p;\n\t" \
        "mbarrier.try_wait.parity.acquire.cta.shared::cta.b64 p, [%1], %2;\n\t" \
        "selp.b32 %0, 1, 0, p;\n\t}" : "=r"(_done) : "r"(_mb), "r"(_p) : "memory"); \
    if (!_done) { \
        asm volatile("{\n\t.reg .pred P1;\n\t" \
            "WL_%=:\n\t" \
            "mbarrier.try_wait.parity.acquire.cta.shared::cta.b64 P1, [%0], %1, 0x989680;\n\t" \
            "@P1 bra.uni WD_%=;\n\t" \
            "bra.uni WL_%=;\n\t" \
            "WD_%=:\n\t}" :: "r"(_mb), "r"(_p) : "memory"); \
    } \
} while (0)

__device__ __forceinline__ uint32_t smem_u32(const void* p) {
    uint32_t a;
    asm("{ .reg .u64 t; cvta.to.shared.u64 t, %1; cvt.u32.u64 %0, t; }" : "=r"(a) : "l"(p));
    return a;
}

// compute over one staged ktile: A[128x32] + B[256x32]; warp tile 64x64 via ldmatrix
__device__ __forceinline__ void tile_compute64(uint32_t stage_addr, float c[4][8][4],
                                               int wm, int wn, int lane) {
    const int rowA = ((lane >> 3) & 1) * 8 + (lane & 7);
    const int colA = (lane >> 4) * 4;
    const int rowB = (lane >> 4) * 8 + (lane & 7);
    const int colB = ((lane >> 3) & 1) * 4;
    const uint32_t aBase = stage_addr + (uint32_t)((wm * 64 + rowA) * LDSS + colA) * 4;
    const uint32_t bBase = stage_addr + (uint32_t)((128 + wn * 64 + rowB) * LDSS + colB) * 4;
    #pragma unroll
    for (int ks = 0; ks < 4; ks++) {
        const uint32_t k0 = ks * 8 * 4;
        uint32_t af[4][4], bf[8][2];
        #pragma unroll
        for (int mt = 0; mt < 4; mt++)
            ldsm_x4(af[mt], aBase + (uint32_t)(mt * 16 * LDSS) * 4 + k0);
        #pragma unroll
        for (int np = 0; np < 4; np++) {
            uint32_t r[4];
            ldsm_x4(r, bBase + (uint32_t)(np * 16 * LDSS) * 4 + k0);
            bf[np * 2][0] = r[0]; bf[np * 2][1] = r[1];
            bf[np * 2 + 1][0] = r[2]; bf[np * 2 + 1][1] = r[3];
        }
        #pragma unroll
        for (int mt = 0; mt < 4; mt++)
            #pragma unroll
            for (int nt = 0; nt < 8; nt++)
                mma8(c[mt][nt], af[mt], bf[nt]);
    }
}

// 4-stage bulk-copy pipeline, one barrier per ktile, 3-ktile lookahead.
// Each thread owns 1-2 row copies per ktile: src0 -> smem row tid; src1 -> row 256+tid (tid<128).
__device__ __forceinline__ void pipe_gemm(uint32_t* sm, uint64_t* mbars,
                                          const float* src0, const float* src1,
                                          int tid, int NT,
                                          float c[4][8][4], int wm, int wn, int lane) {
    const uint32_t smaddr = (uint32_t)__cvta_generic_to_shared(sm);
    uint32_t mb[4];
    #pragma unroll
    for (int s = 0; s < 4; s++) mb[s] = smem_u32(&mbars[s]);
    if (tid == 0) {
        #pragma unroll
        for (int s = 0; s < 4; s++) MBAR_INIT(mb[s], 1);
    }
    __syncthreads();

    const uint32_t d0 = smaddr + (uint32_t)tid * ROWB;
    const uint32_t d1 = smaddr + (uint32_t)(256 + tid) * ROWB;

    // prologue: stages 0..2
    #pragma unroll
    for (int s = 0; s < 3; s++) {
        if (tid == 0) MBAR_EXPECT(mb[s], STAGE_BYTES);
        uint32_t sb = (uint32_t)s * SSTB;
        cpbulk(d0 + sb, src0 + s * 32, mb[s]);
        if (src1) cpbulk(d1 + sb, src1 + s * 32, mb[s]);
    }

    for (int kt = 0; kt < NT; kt++) {
        MBAR_WAIT(mb[kt & 3], (kt >> 2) & 1);
        __syncthreads();
        if (kt + 3 < NT) {
            int ns = (kt + 3) & 3;
            if (tid == 0) MBAR_EXPECT(mb[ns], STAGE_BYTES);
            uint32_t sb = (uint32_t)ns * SSTB;
            cpbulk(d0 + sb, src0 + (kt + 3) * 32, mb[ns]);
            if (src1) cpbulk(d1 + sb, src1 + (kt + 3) * 32, mb[ns]);
        }
        tile_compute64(smaddr + (uint32_t)(kt & 3) * SSTB, c, wm, wn, lane);
    }
}

// ---------------- RMSNorm ----------------
__global__ void rmsnorm_kernel(const float* __restrict__ X,
                               const float* __restrict__ W,
                               float* __restrict__ Y) {
    int t = blockIdx.x;
    int tid = threadIdx.x;
    const float4* xr = (const float4*)(X + (size_t)t * Dc);
    float4 xv = xr[tid];
    float ss = xv.x * xv.x + xv.y * xv.y + xv.z * xv.z + xv.w * xv.w;

    __shared__ float red[8];
    #pragma unroll
    for (int o = 16; o > 0; o >>= 1) ss += __shfl_xor_sync(0xffffffffu, ss, o);
    if ((tid & 31) == 0) red[tid >> 5] = ss;
    __syncthreads();
    float tot = 0.f;
    if (tid < 8) tot = red[tid];
    #pragma unroll
    for (int o = 4; o > 0; o >>= 1) tot += __shfl_xor_sync(0xffu, tot, o);
    __shared__ float s_inv;
    if (tid == 0) s_inv = rsqrtf(tot / (float)Dc + 1e-6f);
    __syncthreads();
    float inv = s_inv;

    float4 wv = ((const float4*)W)[tid];
    float4 out;
    out.x = xv.x * inv * wv.x;
    out.y = xv.y * inv * wv.y;
    out.z = xv.z * inv * wv.z;
    out.w = xv.w * inv * wv.w;
    ((float4*)(Y + (size_t)t * Dc))[tid] = out;
}

// ---------------- dense tf32 GEMM: C = A.W^T, CTA 128x256 ----------------
// mode 0: C = A.W^T     mode 1: C = A.W^T + Res     mode 2: C = silu(Res) * (A.W^T)
__global__ __launch_bounds__(256, 1)
void gemm_mma(const float* __restrict__ A, const float* __restrict__ W,
              const float* __restrict__ Res, float* __restrict__ C,
              int M, int N, int K, int mode) {
    extern __shared__ uint32_t sm[];
    __shared__ __align__(8) uint64_t mbars[4];
    const int tid = threadIdx.x, warp = tid >> 5, lane = tid & 31;
    const int wm = warp & 1, wn = warp >> 1;
    const int m0 = blockIdx.y * 128, n0 = blockIdx.x * 256;

    const float* src0;
    const float* src1;
    if (tid < 128) {
        src0 = A + (size_t)(m0 + tid) * K;
        src1 = W + (size_t)(n0 + 128 + tid) * K;
    } else {
        src0 = W + (size_t)(n0 + tid - 128) * K;
        src1 = nullptr;
    }

    float c[4][8][4];
    #pragma unroll
    for (int a = 0; a < 4; a++)
        #pragma unroll
        for (int b = 0; b < 8; b++)
            #pragma unroll
            for (int d = 0; d < 4; d++) c[a][b][d] = 0.f;

    pipe_gemm(sm, mbars, src0, src1, tid, K >> 5, c, wm, wn, lane);

    const int g = lane >> 2, tg = lane & 3;
    #pragma unroll
    for (int mt = 0; mt < 4; mt++) {
        #pragma unroll
        for (int nt = 0; nt < 8; nt++) {
            int row = m0 + wm * 64 + mt * 16 + g;
            int col = n0 + wn * 64 + nt * 8 + 2 * tg;
            float2 v0 = make_float2(c[mt][nt][0], c[mt][nt][1]);
            float2 v1 = make_float2(c[mt][nt][2], c[mt][nt][3]);
            if (mode == 1) {
                float2 r0 = *(const float2*)&Res[(size_t)row * N + col];
                float2 r1 = *(const float2*)&Res[(size_t)(row + 8) * N + col];
                v0.x += r0.x; v0.y += r0.y; v1.x += r1.x; v1.y += r1.y;
            } else if (mode == 2) {
                float2 r0 = *(const float2*)&Res[(size_t)row * N + col];
                float2 r1 = *(const float2*)&Res[(size_t)(row + 8) * N + col];
                v0.x *= r0.x / (1.f + __expf(-r0.x));
                v0.y *= r0.y / (1.f + __expf(-r0.y));
                v1.x *= r1.x / (1.f + __expf(-r1.x));
                v1.y *= r1.y / (1.f + __expf(-r1.y));
            }
            *(float2*)&C[(size_t)row * N + col] = v0;
            *(float2*)&C[(size_t)(row + 8) * N + col] = v1;
        }
    }
}

// ---------------- gathered tf32 GEMM (mode 0 plain, mode 2 silu-combine) ----------------
__global__ __launch_bounds__(256, 1)
void gemm_gather_mma(const float* __restrict__ Xsrc, const float* __restrict__ Wbase,
                     const float* __restrict__ Res, float* __restrict__ Cout, int mode) {
    const int m0 = blockIdx.y * 128;
    if (m0 >= g_total) return;
    extern __shared__ uint32_t sm[];
    __shared__ __align__(8) uint64_t mbars[4];
    const int tid = threadIdx.x, warp = tid >> 5, lane = tid & 31;
    const int wm = warp & 1, wn = warp >> 1;
    const int n0 = blockIdx.x * 256;
    int e = 0;
    #pragma unroll
    for (int i = 1; i < Ec; i++) if (g_pbase[i] <= m0) e = i;
    const float* W = Wbase + (size_t)e * Ic * Dc;

    const float* src0;
    const float* src1;
    if (tid < 128) {
        src0 = Xsrc + (size_t)g_perm[m0 + tid] * Dc;
        src1 = W + (size_t)(n0 + 128 + tid) * Dc;
    } else {
        src0 = W + (size_t)(n0 + tid - 128) * Dc;
        src1 = nullptr;
    }

    float c[4][8][4];
    #pragma unroll
    for (int a = 0; a < 4; a++)
        #pragma unroll
        for (int b = 0; b < 8; b++)
            #pragma unroll
            for (int d = 0; d < 4; d++) c[a][b][d] = 0.f;

    pipe_gemm(sm, mbars, src0, src1, tid, Dc >> 5, c, wm, wn, lane);

    const int g = lane >> 2, tg = lane & 3;
    #pragma unroll
    for (int mt = 0; mt < 4; mt++) {
        #pragma unroll
        for (int nt = 0; nt < 8; nt++) {
            int row = m0 + wm * 64 + mt * 16 + g;
            int col = n0 + wn * 64 + nt * 8 + 2 * tg;
            float2 v0 = make_float2(c[mt][nt][0], c[mt][nt][1]);
            float2 v1 = make_float2(c[mt][nt][2], c[mt][nt][3]);
            if (mode == 2) {
                float2 r0 = *(const float2*)&Res[(size_t)row * Ic + col];
                float2 r1 = *(const float2*)&Res[(size_t)(row + 8) * Ic + col];
                v0.x *= r0.x / (1.f + __expf(-r0.x));
                v0.y *= r0.y / (1.f + __expf(-r0.y));
                v1.x *= r1.x / (1.f + __expf(-r1.x));
                v1.y *= r1.y / (1.f + __expf(-r1.y));
            }
            *(float2*)&Cout[(size_t)row * Ic + col] = v0;
            *(float2*)&Cout[(size_t)(row + 8) * Ic + col] = v1;
        }
    }
}

// ---------------- routed down GEMM + weighted atomic scatter (into out) ----------------
__global__ __launch_bounds__(256, 1)
void gemm_down_mma(const float* __restrict__ Act, const float* __restrict__ Wbase,
                   float* __restrict__ Out) {
    const int m0 = blockIdx.y * 128;
    if (m0 >= g_total) return;
    extern __shared__ uint32_t sm[];
    __shared__ __align__(8) uint64_t mbars[4];
    const int tid = threadIdx.x, warp = tid >> 5, lane = tid & 31;
    const int wm = warp & 1, wn = warp >> 1;
    const int n0 = blockIdx.x * 256;
    int e = 0;
    #pragma unroll
    for (int i = 1; i < Ec; i++) if (g_pbase[i] <= m0) e = i;
    const float* W = Wbase + (size_t)e * Dc * Ic;

    const float* src0;
    const float* src1;
    if (tid < 128) {
        src0 = Act + (size_t)(m0 + tid) * Ic;
        src1 = W + (size_t)(n0 + 128 + tid) * Ic;
    } else {
        src0 = W + (size_t)(n0 + tid - 128) * Ic;
        src1 = nullptr;
    }

    float c[4][8][4];
    #pragma unroll
    for (int a = 0; a < 4; a++)
        #pragma unroll
        for (int b = 0; b < 8; b++)
            #pragma unroll
            for (int d = 0; d < 4; d++) c[a][b][d] = 0.f;

    pipe_gemm(sm, mbars, src0, src1, tid, Ic >> 5, c, wm, wn, lane);

    const int g = lane >> 2, tg = lane & 3;
    const int eend = g_end[e];
    #pragma unroll
    for (int mt = 0; mt < 4; mt++) {
        int rbase = m0 + wm * 64 + mt * 16 + g;
        #pragma unroll
        for (int half = 0; half < 2; half++) {
            int r = rbase + half * 8;
            if (r < eend) {
                int tok = g_perm[r];
                float wg = g_wgt[r];
                #pragma unroll
                for (int nt = 0; nt < 8; nt++) {
                    int col = n0 + wn * 64 + nt * 8 + 2 * tg;
                    float* Op = Out + (size_t)tok * Dc + col;
                    atomicAdd(&Op[0], wg * c[mt][nt][half * 2 + 0]);
                    atomicAdd(&Op[1], wg * c[mt][nt][half * 2 + 1]);
                }
            }
        }
    }
}

// ---------------- RoPE (in-place on q,k) ----------------
__global__ void rope_kernel(float* __restrict__ Q, float* __restrict__ K) {
    int idx = blockIdx.x * 8 + (threadIdx.x >> 5);
    int lane = threadIdx.x & 31;
    int t = idx / Hc, h = idx % Hc;
    int pos = t & (Sc - 1);
    float inv = expf((float)lane * (-9.210340371976184f / 32.f));
    float ang = (float)pos * inv;
    float sn, cs;
    sincosf(ang, &sn, &cs);
    size_t o = (size_t)t * Dc + h * DHc + lane;
    float q1 = Q[o], q2 = Q[o + 32];
    Q[o]      = q1 * cs - q2 * sn;
    Q[o + 32] = q2 * cs + q1 * sn;
    float k1 = K[o], k2 = K[o + 32];
    K[o]      = k1 * cs - k2 * sn;
    K[o + 32] = k2 * cs + k1 * sn;
}

// ================= mma flash attention =================
constexpr int QST = 68;
constexpr int KST = 68;
constexpr int VST = 72;
constexpr int PST = 36;

__global__ __launch_bounds__(128, 4)
void attn_mma(const float* __restrict__ Q, const float* __restrict__ K,
              const float* __restrict__ V, float* __restrict__ O) {
    const int b = blockIdx.z, h = blockIdx.y, qb = blockIdx.x * 64;
    const int tid = threadIdx.x, w = tid >> 5, lane = tid & 31;
    const int g = lane >> 2, tg = lane & 3;
    __shared__ union { float q[64 * QST]; float p[64 * PST]; } uQ;
    __shared__ float Ks[32 * KST];
    __shared__ float Vs[32 * VST];
    const size_t base = ((size_t)b * Sc) * Dc + (size_t)h * DHc;

    {
        int row = tid >> 1, c0 = (tid & 1) * 32;
        const float* gq = Q + base + (size_t)(qb + row) * Dc + c0;
        #pragma unroll
        for (int i = 0; i < 8; i++)
            *(float4*)&uQ.q[row * QST + c0 + i * 4] = *(const float4*)(gq + i * 4);
    }
    __syncthreads();
    uint32_t aq[8][4];
    #pragma unroll
    for (int ks = 0; ks < 8; ks++) {
        const float* qp = &uQ.q[(w * 16) * QST + ks * 8];
        aq[ks][0] = f2tf32(0.125f * qp[g * QST + tg]);
        aq[ks][1] = f2tf32(0.125f * qp[(g + 8) * QST + tg]);
        aq[ks][2] = f2tf32(0.125f * qp[g * QST + tg + 4]);
        aq[ks][3] = f2tf32(0.125f * qp[(g + 8) * QST + tg + 4]);
    }
    __syncthreads();

    float o[8][4];
    #pragma unroll
    for (int nt = 0; nt < 8; nt++)
        #pragma unroll
        for (int j = 0; j < 4; j++) o[nt][j] = 0.f;
    float m0 = -1e30f, m1 = -1e30f, l0 = 0.f, l1 = 0.f;
    const int r0 = qb + w * 16 + g, r1 = r0 + 8;
    const int qmaxw = qb + w * 16 + 15;
    const int qminw = qb + w * 16;

    for (int t0 = 0; t0 < qb + 64; t0 += 32) {
        {
            int row = tid >> 2, c0 = (tid & 3) * 16;
            const float* gk = K + base + (size_t)(t0 + row) * Dc + c0;
            const float* gv = V + base + (size_t)(t0 + row) * Dc + c0;
            #pragma unroll
            for (int i = 0; i < 4; i++) {
                float4 kv = *(const float4*)(gk + i * 4);
                float4 vv = *(const float4*)(gv + i * 4);
                uint4 ku = make_uint4(f2tf32(kv.x), f2tf32(kv.y), f2tf32(kv.z), f2tf32(kv.w));
                uint4 vu = make_uint4(f2tf32(vv.x), f2tf32(vv.y), f2tf32(vv.z), f2tf32(vv.w));
                *(uint4*)&Ks[row * KST + c0 + i * 4] = ku;
                *(uint4*)&Vs[row * VST + c0 + i * 4] = vu;
            }
        }
        __syncthreads();
        if (t0 <= qmaxw) {
            float s[4][4];
            #pragma unroll
            for (int nt = 0; nt < 4; nt++)
                #pragma unroll
                for (int j = 0; j < 4; j++) s[nt][j] = 0.f;
            const uint32_t* Ku = (const uint32_t*)Ks;
            #pragma unroll
            for (int ks = 0; ks < 8; ks++) {
                #pragma unroll
                for (int nt = 0; nt < 4; nt++) {
                    uint32_t bb[2];
                    bb[0] = Ku[(nt * 8 + g) * KST + ks * 8 + tg];
                    bb[1] = Ku[(nt * 8 + g) * KST + ks * 8 + tg + 4];
                    mma8(s[nt], aq[ks], bb);
                }
            }
            if (t0 + 31 > qminw) {
                #pragma unroll
                for (int nt = 0; nt < 4; nt++) {
                    int k0 = t0 + nt * 8 + 2 * tg;
                    if (k0 > r0)     s[nt][0] = -1e9f;
                    if (k0 + 1 > r0) s[nt][1] = -1e9f;
                    if (k0 > r1)     s[nt][2] = -1e9f;
                    if (k0 + 1 > r1) s[nt][3] = -1e9f;
                }
            }
            float tm0 = fmaxf(fmaxf(s[0][0], s[0][1]), fmaxf(s[1][0], s[1][1]));
            tm0 = fmaxf(tm0, fmaxf(fmaxf(s[2][0], s[2][1]), fmaxf(s[3][0], s[3][1])));
            float tm1 = fmaxf(fmaxf(s[0][2], s[0][3]), fmaxf(s[1][2], s[1][3]));
            tm1 = fmaxf(tm1, fmaxf(fmaxf(s[2][2], s[2][3]), fmaxf(s[3][2], s[3][3])));
            #pragma unroll
            for (int ofs = 1; ofs <= 2; ofs <<= 1) {
                tm0 = fmaxf(tm0, __shfl_xor_sync(0xffffffffu, tm0, ofs));
                tm1 = fmaxf(tm1, __shfl_xor_sync(0xffffffffu, tm1, ofs));
            }
            float mn0 = fmaxf(m0, tm0), mn1 = fmaxf(m1, tm1);
            float sc0 = __expf(m0 - mn0), sc1 = __expf(m1 - mn1);
            float lp0 = 0.f, lp1 = 0.f;
            uint32_t* Pu = (uint32_t*)uQ.p;
            #pragma unroll
            for (int nt = 0; nt < 4; nt++) {
                float p0 = __expf(s[nt][0] - mn0), p1 = __expf(s[nt][1] - mn0);
                float p2 = __expf(s[nt][2] - mn1), p3 = __expf(s[nt][3] - mn1);
                lp0 += p0 + p1; lp1 += p2 + p3;
                *(uint2*)&Pu[(w * 16 + g) * PST + nt * 8 + 2 * tg] =
                    make_uint2(f2tf32(p0), f2tf32(p1));
                *(uint2*)&Pu[(w * 16 + g + 8) * PST + nt * 8 + 2 * tg] =
                    make_uint2(f2tf32(p2), f2tf32(p3));
            }
            l0 = l0 * sc0 + lp0;
            l1 = l1 * sc1 + lp1;
            #pragma unroll
            for (int nt = 0; nt < 8; nt++) {
                o[nt][0] *= sc0; o[nt][1] *= sc0; o[nt][2] *= sc1; o[nt][3] *= sc1;
            }
            m0 = mn0; m1 = mn1;
            __syncwarp();
            const uint32_t* Vu = (const uint32_t*)Vs;
            #pragma unroll
            for (int ks = 0; ks < 4; ks++) {
                uint32_t ap[4];
                const uint32_t* pb = Pu + (w * 16) * PST + ks * 8;
                ap[0] = pb[g * PST + tg];
                ap[1] = pb[(g + 8) * PST + tg];
                ap[2] = pb[g * PST + tg + 4];
                ap[3] = pb[(g + 8) * PST + tg + 4];
                #pragma unroll
                for (int nt = 0; nt < 8; nt++) {
                    uint32_t bb[2];
                    bb[0] = Vu[(ks * 8 + tg) * VST + nt * 8 + g];
                    bb[1] = Vu[(ks * 8 + tg + 4) * VST + nt * 8 + g];
                    mma8(o[nt], ap, bb);
                }
            }
        }
        __syncthreads();
    }
    #pragma unroll
    for (int ofs = 1; ofs <= 2; ofs <<= 1) {
        l0 += __shfl_xor_sync(0xffffffffu, l0, ofs);
        l1 += __shfl_xor_sync(0xffffffffu, l1, ofs);
    }
    float i0 = 1.f / l0, i1 = 1.f / l1;
    float* o0 = O + base + (size_t)r0 * Dc;
    float* o1 = O + base + (size_t)r1 * Dc;
    #pragma unroll
    for (int nt = 0; nt < 8; nt++) {
        *(float2*)&o0[nt * 8 + 2 * tg] = make_float2(o[nt][0] * i0, o[nt][1] * i0);
        *(float2*)&o1[nt * 8 + 2 * tg] = make_float2(o[nt][2] * i1, o[nt][3] * i1);
    }
}

// ---------------- meta reset (perm + counters only) ----------------
__global__ void zero_meta() {
    int i = blockIdx.x * blockDim.x + threadIdx.x;
    if (i < PERM_MAX) { g_perm[i] = 0; g_wgt[i] = 0.f; }
    if (i < Ec) { g_cnt[i] = 0; g_fill[i] = 0; }
}

// ---------------- router ----------------
__global__ void router_kernel(const float* __restrict__ RW, const float* __restrict__ BIAS) {
    int t = blockIdx.x * 8 + (threadIdx.x >> 5);
    int lane = threadIdx.x & 31;
    const float* x = g_A + (size_t)t * Dc;
    float acc[Ec];
    #pragma unroll
    for (int e = 0; e < Ec; e++) acc[e] = 0.f;
    for (int d = lane; d < Dc; d += 32) {
        float xv = x[d];
        #pragma unroll
        for (int e = 0; e < Ec; e++) acc[e] = fmaf(xv, RW[e * Dc + d], acc[e]);
    }
    #pragma unroll
    for (int e = 0; e < Ec; e++) {
        #pragma unroll
        for (int o = 16; o > 0; o >>= 1) acc[e] += __shfl_xor_sync(0xffffffffu, acc[e], o);
    }
    if (lane == 0) {
        float gg[Ec];
        #pragma unroll
        for (int e = 0; e < Ec; e++) gg[e] = 1.f / (1.f + expf(-(acc[e] + BIAS[e])));
        int i0 = 0; float g0 = gg[0];
        #pragma unroll
        for (int e = 1; e < Ec; e++) if (gg[e] > g0) { g0 = gg[e]; i0 = e; }
        int i1 = -1; float g1 = -1e30f;
        #pragma unroll
        for (int e = 0; e < Ec; e++) if (e != i0 && gg[e] > g1) { g1 = gg[e]; i1 = e; }
        float s = g0 + g1 + 1e-9f;
        g_tok_e[2 * t] = i0;     g_tok_w[2 * t] = g0 / s;
        g_tok_e[2 * t + 1] = i1; g_tok_w[2 * t + 1] = g1 / s;
        atomicAdd(&g_cnt[i0], 1);
        atomicAdd(&g_cnt[i1], 1);
    }
}

__global__ void scan_kernel() {
    int b = 0;
    for (int e = 0; e < Ec; e++) {
        g_pbase[e] = b;
        g_end[e] = b + g_cnt[e];
        b += (g_cnt[e] + 127) & ~127;
    }
    g_pbase[Ec] = b;
    g_total = b;
}

__global__ void fill_kernel() {
    int a = blockIdx.x * blockDim.x + threadIdx.x;
    if (a >= 2 * Tc) return;
    int e = g_tok_e[a];
    float w = g_tok_w[a];
    int pos = atomicAdd(&g_fill[e], 1);
    int r = g_pbase[e] + pos;
    g_perm[r] = a >> 1;
    g_wgt[r] = w;
}

// ---------------- launcher ----------------
extern "C" void kernel_launch(void* const* d_in, const int* in_sizes, int n_in,
                              void* d_out, int out_size) {
    const float* x   = (const float*)d_in[0];
    const float* n1w = (const float*)d_in[1];
    const float* wq  = (const float*)d_in[2];
    const float* wk  = (const float*)d_in[3];
    const float* wv  = (const float*)d_in[4];
    const float* wo  = (const float*)d_in[5];
    const float* n2w = (const float*)d_in[6];
    const float* rw  = (const float*)d_in[7];
    const float* eb  = (const float*)d_in[8];
    const float* sg  = (const float*)d_in[9];
    const float* su  = (const float*)d_in[10];
    const float* sd  = (const float*)d_in[11];
    const float* eg  = (const float*)d_in[12];
    const float* eu  = (const float*)d_in[13];
    const float* ed  = (const float*)d_in[14];
    float* out = (float*)d_out;

    float *pA, *pB, *pC, *pD, *pE, *pF, *pCG, *pCU;
    cudaGetSymbolAddress((void**)&pA, g_A);
    cudaGetSymbolAddress((void**)&pB, g_B);
    cudaGetSymbolAddress((void**)&pC, g_C);
    cudaGetSymbolAddress((void**)&pD, g_D);
    cudaGetSymbolAddress((void**)&pE, g_E);
    cudaGetSymbolAddress((void**)&pF, g_F);
    cudaGetSymbolAddress((void**)&pCG, g_cg);
    cudaGetSymbolAddress((void**)&pCU, g_cu);

    cudaFuncSetAttribute(gemm_mma, cudaFuncAttributeMaxDynamicSharedMemorySize, SMEM_GEMM);
    cudaFuncSetAttribute(gemm_gather_mma, cudaFuncAttributeMaxDynamicSharedMemorySize, SMEM_GEMM);
    cudaFuncSetAttribute(gemm_down_mma, cudaFuncAttributeMaxDynamicSharedMemorySize, SMEM_GEMM);

    dim3 gDen(Dc / 256, Tc / 128);          // (4, 64)
    dim3 gGath(Ic / 256, PERM_MAX / 128);   // (4, 144)
    dim3 gDown(Dc / 256, PERM_MAX / 128);

    // attention branch
    rmsnorm_kernel<<<Tc, 256>>>(x, n1w, pA);
    gemm_mma<<<gDen, 256, SMEM_GEMM>>>(pA, wq, nullptr, pB, Tc, Dc, Dc, 0);
    gemm_mma<<<gDen, 256, SMEM_GEMM>>>(pA, wk, nullptr, pC, Tc, Dc, Dc, 0);
    gemm_mma<<<gDen, 256, SMEM_GEMM>>>(pA, wv, nullptr, pD, Tc, Dc, Dc, 0);
    rope_kernel<<<Tc * Hc / 8, 256>>>(pB, pC);
    attn_mma<<<dim3(Sc / 64, Hc, Bc), 128>>>(pB, pC, pD, pE);
    gemm_mma<<<gDen, 256, SMEM_GEMM>>>(pE, wo, x, pF, Tc, Dc, Dc, 1);   // x1 = ctx.wo^T + x

    // MoE branch
    rmsnorm_kernel<<<Tc, 256>>>(pF, n2w, pA);                            // h2
    gemm_mma<<<gDen, 256, SMEM_GEMM>>>(pA, sg, nullptr, pB, Tc, Ic, Dc, 0);       // gate
    gemm_mma<<<gDen, 256, SMEM_GEMM>>>(pA, su, pB, pB, Tc, Ic, Dc, 2);            // act = silu(gate)*up
    gemm_mma<<<gDen, 256, SMEM_GEMM>>>(pB, sd, pF, out, Tc, Dc, Ic, 1);           // out = x1 + shared

    zero_meta<<<(PERM_MAX + 255) / 256, 256>>>();
    router_kernel<<<Tc / 8, 256>>>(rw, eb);
    scan_kernel<<<1, 1>>>();
    fill_kernel<<<(2 * Tc + 255) / 256, 256>>>();
    gemm_gather_mma<<<gGath, 256, SMEM_GEMM>>>(pA, eg, nullptr, pCG, 0);          // routed gate
    gemm_gather_mma<<<gGath, 256, SMEM_GEMM>>>(pA, eu, pCG, pCG, 2);              // act = silu(g)*u
    gemm_down_mma<<<gDown, 256, SMEM_GEMM>>>(pCG, ed, out);                       // out += routed

    (void)in_sizes; (void)n_in; (void)out_size;
}

// round 15
// speedup vs baseline: 1.0521x; 1.0521x over previous
#include <cuda_runtime.h>
#include <math.h>
#include <float.h>
#include <stdint.h>

// ---------------- problem constants ----------------
constexpr int Bc  = 4;
constexpr int Sc  = 2048;
constexpr int Dc  = 1024;
constexpr int Hc  = 16;
constexpr int DHc = 64;
constexpr int Ec  = 16;
constexpr int Ic  = 1024;
constexpr int Tc  = Bc * Sc;                 // 8192 tokens
constexpr int PERM_MAX = 2 * Tc + 128 * Ec;  // 18432, multiple of 128

constexpr int LDSS = 36;                       // smem row stride (u32)
constexpr int SST  = 384 * LDSS;               // u32 per stage (128 A rows + 256 B rows)
constexpr int SMEM_GEMM = 4 * SST * 4;         // 221184 B (4 stages)

// ---------------- scratch (device globals; no allocs allowed) ----------------
__device__ float g_A[Tc * Dc];
__device__ float g_B[Tc * Ic];
__device__ float g_C[Tc * Ic];
__device__ float g_D[Tc * Dc];
__device__ float g_E[Tc * Dc];
__device__ float g_F[Tc * Dc];
__device__ float g_cg[PERM_MAX * Ic];

__device__ int   g_cnt[Ec];
__device__ int   g_fill[Ec];
__device__ int   g_pbase[Ec + 1];
__device__ int   g_end[Ec];
__device__ int   g_total;
__device__ int   g_perm[PERM_MAX];
__device__ float g_wgt[PERM_MAX];
__device__ int   g_tok_e[2 * Tc];
__device__ float g_tok_w[2 * Tc];

// ---------------- mma / async helpers ----------------
__device__ __forceinline__ uint32_t f2tf32(float f) {
    uint32_t r;
    asm("cvt.rna.tf32.f32 %0, %1;" : "=r"(r) : "f"(f));
    return r;
}

__device__ __forceinline__ void mma8(float* c, const uint32_t* a, const uint32_t* b) {
    asm volatile(
        "mma.sync.aligned.m16n8k8.row.col.f32.tf32.tf32.f32 "
        "{%0,%1,%2,%3}, {%4,%5,%6,%7}, {%8,%9}, {%0,%1,%2,%3};"
        : "+f"(c[0]), "+f"(c[1]), "+f"(c[2]), "+f"(c[3])
        : "r"(a[0]), "r"(a[1]), "r"(a[2]), "r"(a[3]), "r"(b[0]), "r"(b[1]));
}

__device__ __forceinline__ void ldsm_x4(uint32_t* r, uint32_t addr) {
    asm volatile("ldmatrix.sync.aligned.m8n8.x4.shared.b16 {%0,%1,%2,%3}, [%4];"
        : "=r"(r[0]), "=r"(r[1]), "=r"(r[2]), "=r"(r[3]) : "r"(addr));
}

__device__ __forceinline__ void cp16(uint32_t dst, const void* src) {
    asm volatile("cp.async.cg.shared.global [%0], [%1], 16;" :: "r"(dst), "l"(src));
}
#define CP_COMMIT() asm volatile("cp.async.commit_group;" ::: "memory")
#define CP_WAIT(n)  asm volatile("cp.async.wait_group %0;" :: "n"(n) : "memory")

// compute over one staged ktile: A[128x32] + B[256x32]; warp tile 64x64 via ldmatrix
__device__ __forceinline__ void tile_compute64(uint32_t stage_addr, float c[4][8][4],
                                               int wm, int wn, int lane) {
    const int rowA = ((lane >> 3) & 1) * 8 + (lane & 7);
    const int colA = (lane >> 4) * 4;
    const int rowB = (lane >> 4) * 8 + (lane & 7);
    const int colB = ((lane >> 3) & 1) * 4;
    const uint32_t aBase = stage_addr + (uint32_t)((wm * 64 + rowA) * LDSS + colA) * 4;
    const uint32_t bBase = stage_addr + (uint32_t)((128 + wn * 64 + rowB) * LDSS + colB) * 4;
    #pragma unroll
    for (int ks = 0; ks < 4; ks++) {
        const uint32_t k0 = ks * 8 * 4;
        uint32_t af[4][4], bf[8][2];
        #pragma unroll
        for (int mt = 0; mt < 4; mt++)
            ldsm_x4(af[mt], aBase + (uint32_t)(mt * 16 * LDSS) * 4 + k0);
        #pragma unroll
        for (int np = 0; np < 4; np++) {
            uint32_t r[4];
            ldsm_x4(r, bBase + (uint32_t)(np * 16 * LDSS) * 4 + k0);
            bf[np * 2][0] = r[0]; bf[np * 2][1] = r[1];
            bf[np * 2 + 1][0] = r[2]; bf[np * 2 + 1][1] = r[3];
        }
        #pragma unroll
        for (int mt = 0; mt < 4; mt++)
            #pragma unroll
            for (int nt = 0; nt < 8; nt++)
                mma8(c[mt][nt], af[mt], bf[nt]);
    }
}

// 4-stage cp.async pipeline, one barrier per ktile, 3-ktile lookahead.
__device__ __forceinline__ void pipe_gemm(uint32_t* sm, const float* pa, const float* pb0,
                                          const float* pb1, int tid, int NT,
                                          float c[4][8][4], int wm, int wn, int lane) {
    const uint32_t smaddr = (uint32_t)__cvta_generic_to_shared(sm);
    const uint32_t aoff  = ((uint32_t)((tid >> 1) * LDSS + (tid & 1) * 16)) * 4;
    const uint32_t b0off = aoff + 128u * LDSS * 4;
    const uint32_t b1off = aoff + 256u * LDSS * 4;

    // prologue: stages 0..2
    #pragma unroll
    for (int s = 0; s < 3; s++) {
        uint32_t sb = smaddr + (uint32_t)s * SST * 4;
        #pragma unroll
        for (int i = 0; i < 4; i++) cp16(sb + aoff + i * 16, pa + s * 32 + i * 4);
        #pragma unroll
        for (int i = 0; i < 4; i++) cp16(sb + b0off + i * 16, pb0 + s * 32 + i * 4);
        #pragma unroll
        for (int i = 0; i < 4; i++) cp16(sb + b1off + i * 16, pb1 + s * 32 + i * 4);
        CP_COMMIT();
    }

    int stage = 0;
    for (int kt = 0; kt < NT; kt++) {
        int rem = NT - kt - 1;
        if (rem >= 2) { CP_WAIT(2); } else if (rem == 1) { CP_WAIT(1); } else { CP_WAIT(0); }
        __syncthreads();
        if (kt + 3 < NT) {
            int ns = stage + 3; if (ns >= 4) ns -= 4;
            uint32_t sb = smaddr + (uint32_t)ns * SST * 4;
            const float* qa  = pa  + (kt + 3) * 32;
            const float* qb0 = pb0 + (kt + 3) * 32;
            const float* qb1 = pb1 + (kt + 3) * 32;
            #pragma unroll
            for (int i = 0; i < 4; i++) cp16(sb + aoff + i * 16, qa + i * 4);
            #pragma unroll
            for (int i = 0; i < 4; i++) cp16(sb + b0off + i * 16, qb0 + i * 4);
            #pragma unroll
            for (int i = 0; i < 4; i++) cp16(sb + b1off + i * 16, qb1 + i * 4);
            CP_COMMIT();
        }
        tile_compute64(smaddr + (uint32_t)stage * SST * 4, c, wm, wn, lane);
        if (++stage == 4) stage = 0;
    }
}

// ---------------- RMSNorm ----------------
__global__ void rmsnorm_kernel(const float* __restrict__ X,
                               const float* __restrict__ W,
                               float* __restrict__ Y) {
    int t = blockIdx.x;
    int tid = threadIdx.x;
    const float4* xr = (const float4*)(X + (size_t)t * Dc);
    float4 xv = xr[tid];
    float ss = xv.x * xv.x + xv.y * xv.y + xv.z * xv.z + xv.w * xv.w;

    __shared__ float red[8];
    #pragma unroll
    for (int o = 16; o > 0; o >>= 1) ss += __shfl_xor_sync(0xffffffffu, ss, o);
    if ((tid & 31) == 0) red[tid >> 5] = ss;
    __syncthreads();
    float tot = 0.f;
    if (tid < 8) tot = red[tid];
    #pragma unroll
    for (int o = 4; o > 0; o >>= 1) tot += __shfl_xor_sync(0xffu, tot, o);
    __shared__ float s_inv;
    if (tid == 0) s_inv = rsqrtf(tot / (float)Dc + 1e-6f);
    __syncthreads();
    float inv = s_inv;

    float4 wv = ((const float4*)W)[tid];
    float4 out;
    out.x = xv.x * inv * wv.x;
    out.y = xv.y * inv * wv.y;
    out.z = xv.z * inv * wv.z;
    out.w = xv.w * inv * wv.w;
    ((float4*)(Y + (size_t)t * Dc))[tid] = out;
}

// ---------------- dense tf32 GEMM: C = A.W^T, CTA 128x256 ----------------
// mode 0: C = A.W^T   mode 1: C = A.W^T + Res   mode 2: C = silu(Res) * (A.W^T)
__global__ __launch_bounds__(256, 1)
void gemm_mma(const float* __restrict__ A, const float* __restrict__ W,
              const float* __restrict__ Res, float* __restrict__ C,
              int M, int N, int K, int mode) {
    extern __shared__ uint32_t sm[];
    const int tid = threadIdx.x, warp = tid >> 5, lane = tid & 31;
    const int wm = warp & 1, wn = warp >> 1;
    const int m0 = blockIdx.y * 128, n0 = blockIdx.x * 256;
    const int hrow = tid >> 1, hcol = (tid & 1) * 16;

    const float* pa  = A + (size_t)(m0 + hrow) * K + hcol;
    const float* pb0 = W + (size_t)(n0 + hrow) * K + hcol;
    const float* pb1 = W + (size_t)(n0 + 128 + hrow) * K + hcol;

    float c[4][8][4];
    #pragma unroll
    for (int a = 0; a < 4; a++)
        #pragma unroll
        for (int b = 0; b < 8; b++)
            #pragma unroll
            for (int d = 0; d < 4; d++) c[a][b][d] = 0.f;

    pipe_gemm(sm, pa, pb0, pb1, tid, K >> 5, c, wm, wn, lane);

    const int g = lane >> 2, tg = lane & 3;
    #pragma unroll
    for (int mt = 0; mt < 4; mt++) {
        #pragma unroll
        for (int nt = 0; nt < 8; nt++) {
            int row = m0 + wm * 64 + mt * 16 + g;
            int col = n0 + wn * 64 + nt * 8 + 2 * tg;
            float2 v0 = make_float2(c[mt][nt][0], c[mt][nt][1]);
            float2 v1 = make_float2(c[mt][nt][2], c[mt][nt][3]);
            if (mode == 1) {
                float2 r0 = *(const float2*)&Res[(size_t)row * N + col];
                float2 r1 = *(const float2*)&Res[(size_t)(row + 8) * N + col];
                v0.x += r0.x; v0.y += r0.y; v1.x += r1.x; v1.y += r1.y;
            } else if (mode == 2) {
                float2 r0 = *(const float2*)&Res[(size_t)row * N + col];
                float2 r1 = *(const float2*)&Res[(size_t)(row + 8) * N + col];
                v0.x *= r0.x / (1.f + __expf(-r0.x));
                v0.y *= r0.y / (1.f + __expf(-r0.y));
                v1.x *= r1.x / (1.f + __expf(-r1.x));
                v1.y *= r1.y / (1.f + __expf(-r1.y));
            }
            *(float2*)&C[(size_t)row * N + col] = v0;
            *(float2*)&C[(size_t)(row + 8) * N + col] = v1;
        }
    }
}

// ---------------- gathered tf32 GEMM (mode 0 plain, mode 2 silu-combine) ----------------
__global__ __launch_bounds__(256, 1)
void gemm_gather_mma(const float* __restrict__ Xsrc, const float* __restrict__ Wbase,
                     const float* __restrict__ Res, float* __restrict__ Cout, int mode) {
    const int m0 = blockIdx.y * 128;
    if (m0 >= g_total) return;
    extern __shared__ uint32_t sm[];
    const int tid = threadIdx.x, warp = tid >> 5, lane = tid & 31;
    const int wm = warp & 1, wn = warp >> 1;
    const int n0 = blockIdx.x * 256;
    int e = 0;
    #pragma unroll
    for (int i = 1; i < Ec; i++) if (g_pbase[i] <= m0) e = i;
    const float* W = Wbase + (size_t)e * Ic * Dc;

    const int hrow = tid >> 1, hcol = (tid & 1) * 16;
    const int tok = g_perm[m0 + hrow];
    const float* pa  = Xsrc + (size_t)tok * Dc + hcol;
    const float* pb0 = W + (size_t)(n0 + hrow) * Dc + hcol;
    const float* pb1 = W + (size_t)(n0 + 128 + hrow) * Dc + hcol;

    float c[4][8][4];
    #pragma unroll
    for (int a = 0; a < 4; a++)
        #pragma unroll
        for (int b = 0; b < 8; b++)
            #pragma unroll
            for (int d = 0; d < 4; d++) c[a][b][d] = 0.f;

    pipe_gemm(sm, pa, pb0, pb1, tid, Dc >> 5, c, wm, wn, lane);

    const int g = lane >> 2, tg = lane & 3;
    #pragma unroll
    for (int mt = 0; mt < 4; mt++) {
        #pragma unroll
        for (int nt = 0; nt < 8; nt++) {
            int row = m0 + wm * 64 + mt * 16 + g;
            int col = n0 + wn * 64 + nt * 8 + 2 * tg;
            float2 v0 = make_float2(c[mt][nt][0], c[mt][nt][1]);
            float2 v1 = make_float2(c[mt][nt][2], c[mt][nt][3]);
            if (mode == 2) {
                float2 r0 = *(const float2*)&Res[(size_t)row * Ic + col];
                float2 r1 = *(const float2*)&Res[(size_t)(row + 8) * Ic + col];
                v0.x *= r0.x / (1.f + __expf(-r0.x));
                v0.y *= r0.y / (1.f + __expf(-r0.y));
                v1.x *= r1.x / (1.f + __expf(-r1.x));
                v1.y *= r1.y / (1.f + __expf(-r1.y));
            }
            *(float2*)&Cout[(size_t)row * Ic + col] = v0;
            *(float2*)&Cout[(size_t)(row + 8) * Ic + col] = v1;
        }
    }
}

// ---------------- routed down GEMM + weighted atomic scatter (into out) ----------------
__global__ __launch_bounds__(256, 1)
void gemm_down_mma(const float* __restrict__ Act, const float* __restrict__ Wbase,
                   float* __restrict__ Out) {
    const int m0 = blockIdx.y * 128;
    if (m0 >= g_total) return;
    extern __shared__ uint32_t sm[];
    const int tid = threadIdx.x, warp = tid >> 5, lane = tid & 31;
    const int wm = warp & 1, wn = warp >> 1;
    const int n0 = blockIdx.x * 256;
    int e = 0;
    #pragma unroll
    for (int i = 1; i < Ec; i++) if (g_pbase[i] <= m0) e = i;
    const float* W = Wbase + (size_t)e * Dc * Ic;

    const int hrow = tid >> 1, hcol = (tid & 1) * 16;
    const float* pa  = Act + (size_t)(m0 + hrow) * Ic + hcol;
    const float* pb0 = W + (size_t)(n0 + hrow) * Ic + hcol;
    const float* pb1 = W + (size_t)(n0 + 128 + hrow) * Ic + hcol;

    float c[4][8][4];
    #pragma unroll
    for (int a = 0; a < 4; a++)
        #pragma unroll
        for (int b = 0; b < 8; b++)
            #pragma unroll
            for (int d = 0; d < 4; d++) c[a][b][d] = 0.f;

    pipe_gemm(sm, pa, pb0, pb1, tid, Ic >> 5, c, wm, wn, lane);

    const int g = lane >> 2, tg = lane & 3;
    const int eend = g_end[e];
    #pragma unroll
    for (int mt = 0; mt < 4; mt++) {
        int rbase = m0 + wm * 64 + mt * 16 + g;
        #pragma unroll
        for (int half = 0; half < 2; half++) {
            int r = rbase + half * 8;
            if (r < eend) {
                int tok = g_perm[r];
                float wg = g_wgt[r];
                #pragma unroll
                for (int nt = 0; nt < 8; nt++) {
                    int col = n0 + wn * 64 + nt * 8 + 2 * tg;
                    float* Op = Out + (size_t)tok * Dc + col;
                    atomicAdd(&Op[0], wg * c[mt][nt][half * 2 + 0]);
                    atomicAdd(&Op[1], wg * c[mt][nt][half * 2 + 1]);
                }
            }
        }
    }
}

// ---------------- RoPE (in-place on q,k) ----------------
__global__ void rope_kernel(float* __restrict__ Q, float* __restrict__ K) {
    int idx = blockIdx.x * 8 + (threadIdx.x >> 5);
    int lane = threadIdx.x & 31;
    int t = idx / Hc, h = idx % Hc;
    int pos = t & (Sc - 1);
    float inv = expf((float)lane * (-9.210340371976184f / 32.f));
    float ang = (float)pos * inv;
    float sn, cs;
    sincosf(ang, &sn, &cs);
    size_t o = (size_t)t * Dc + h * DHc + lane;
    float q1 = Q[o], q2 = Q[o + 32];
    Q[o]      = q1 * cs - q2 * sn;
    Q[o + 32] = q2 * cs + q1 * sn;
    float k1 = K[o], k2 = K[o + 32];
    K[o]      = k1 * cs - k2 * sn;
    K[o + 32] = k2 * cs + k1 * sn;
}

// ================= mma flash attention =================
constexpr int QST = 68;
constexpr int KST = 68;
constexpr int VST = 72;
constexpr int PST = 36;

__global__ __launch_bounds__(128, 4)
void attn_mma(const float* __restrict__ Q, const float* __restrict__ K,
              const float* __restrict__ V, float* __restrict__ O) {
    const int b = blockIdx.z, h = blockIdx.y, qb = blockIdx.x * 64;
    const int tid = threadIdx.x, w = tid >> 5, lane = tid & 31;
    const int g = lane >> 2, tg = lane & 3;
    __shared__ union { float q[64 * QST]; float p[64 * PST]; } uQ;
    __shared__ float Ks[32 * KST];
    __shared__ float Vs[32 * VST];
    const size_t base = ((size_t)b * Sc) * Dc + (size_t)h * DHc;

    {
        int row = tid >> 1, c0 = (tid & 1) * 32;
        const float* gq = Q + base + (size_t)(qb + row) * Dc + c0;
        #pragma unroll
        for (int i = 0; i < 8; i++)
            *(float4*)&uQ.q[row * QST + c0 + i * 4] = *(const float4*)(gq + i * 4);
    }
    __syncthreads();
    uint32_t aq[8][4];
    #pragma unroll
    for (int ks = 0; ks < 8; ks++) {
        const float* qp = &uQ.q[(w * 16) * QST + ks * 8];
        aq[ks][0] = f2tf32(0.125f * qp[g * QST + tg]);
        aq[ks][1] = f2tf32(0.125f * qp[(g + 8) * QST + tg]);
        aq[ks][2] = f2tf32(0.125f * qp[g * QST + tg + 4]);
        aq[ks][3] = f2tf32(0.125f * qp[(g + 8) * QST + tg + 4]);
    }
    __syncthreads();

    float o[8][4];
    #pragma unroll
    for (int nt = 0; nt < 8; nt++)
        #pragma unroll
        for (int j = 0; j < 4; j++) o[nt][j] = 0.f;
    float m0 = -1e30f, m1 = -1e30f, l0 = 0.f, l1 = 0.f;
    const int r0 = qb + w * 16 + g, r1 = r0 + 8;
    const int qmaxw = qb + w * 16 + 15;
    const int qminw = qb + w * 16;

    for (int t0 = 0; t0 < qb + 64; t0 += 32) {
        {
            int row = tid >> 2, c0 = (tid & 3) * 16;
            const float* gk = K + base + (size_t)(t0 + row) * Dc + c0;
            const float* gv = V + base + (size_t)(t0 + row) * Dc + c0;
            #pragma unroll
            for (int i = 0; i < 4; i++) {
                float4 kv = *(const float4*)(gk + i * 4);
                float4 vv = *(const float4*)(gv + i * 4);
                uint4 ku = make_uint4(f2tf32(kv.x), f2tf32(kv.y), f2tf32(kv.z), f2tf32(kv.w));
                uint4 vu = make_uint4(f2tf32(vv.x), f2tf32(vv.y), f2tf32(vv.z), f2tf32(vv.w));
                *(uint4*)&Ks[row * KST + c0 + i * 4] = ku;
                *(uint4*)&Vs[row * VST + c0 + i * 4] = vu;
            }
        }
        __syncthreads();
        if (t0 <= qmaxw) {
            float s[4][4];
            #pragma unroll
            for (int nt = 0; nt < 4; nt++)
                #pragma unroll
                for (int j = 0; j < 4; j++) s[nt][j] = 0.f;
            const uint32_t* Ku = (const uint32_t*)Ks;
            #pragma unroll
            for (int ks = 0; ks < 8; ks++) {
                #pragma unroll
                for (int nt = 0; nt < 4; nt++) {
                    uint32_t bb[2];
                    bb[0] = Ku[(nt * 8 + g) * KST + ks * 8 + tg];
                    bb[1] = Ku[(nt * 8 + g) * KST + ks * 8 + tg + 4];
                    mma8(s[nt], aq[ks], bb);
                }
            }
            if (t0 + 31 > qminw) {
                #pragma unroll
                for (int nt = 0; nt < 4; nt++) {
                    int k0 = t0 + nt * 8 + 2 * tg;
                    if (k0 > r0)     s[nt][0] = -1e9f;
                    if (k0 + 1 > r0) s[nt][1] = -1e9f;
                    if (k0 > r1)     s[nt][2] = -1e9f;
                    if (k0 + 1 > r1) s[nt][3] = -1e9f;
                }
            }
            float tm0 = fmaxf(fmaxf(s[0][0], s[0][1]), fmaxf(s[1][0], s[1][1]));
            tm0 = fmaxf(tm0, fmaxf(fmaxf(s[2][0], s[2][1]), fmaxf(s[3][0], s[3][1])));
            float tm1 = fmaxf(fmaxf(s[0][2], s[0][3]), fmaxf(s[1][2], s[1][3]));
            tm1 = fmaxf(tm1, fmaxf(fmaxf(s[2][2], s[2][3]), fmaxf(s[3][2], s[3][3])));
            #pragma unroll
            for (int ofs = 1; ofs <= 2; ofs <<= 1) {
                tm0 = fmaxf(tm0, __shfl_xor_sync(0xffffffffu, tm0, ofs));
                tm1 = fmaxf(tm1, __shfl_xor_sync(0xffffffffu, tm1, ofs));
            }
            float mn0 = fmaxf(m0, tm0), mn1 = fmaxf(m1, tm1);
            float sc0 = __expf(m0 - mn0), sc1 = __expf(m1 - mn1);
            float lp0 = 0.f, lp1 = 0.f;
            uint32_t* Pu = (uint32_t*)uQ.p;
            #pragma unroll
            for (int nt = 0; nt < 4; nt++) {
                float p0 = __expf(s[nt][0] - mn0), p1 = __expf(s[nt][1] - mn0);
                float p2 = __expf(s[nt][2] - mn1), p3 = __expf(s[nt][3] - mn1);
                lp0 += p0 + p1; lp1 += p2 + p3;
                *(uint2*)&Pu[(w * 16 + g) * PST + nt * 8 + 2 * tg] =
                    make_uint2(f2tf32(p0), f2tf32(p1));
                *(uint2*)&Pu[(w * 16 + g + 8) * PST + nt * 8 + 2 * tg] =
                    make_uint2(f2tf32(p2), f2tf32(p3));
            }
            l0 = l0 * sc0 + lp0;
            l1 = l1 * sc1 + lp1;
            #pragma unroll
            for (int nt = 0; nt < 8; nt++) {
                o[nt][0] *= sc0; o[nt][1] *= sc0; o[nt][2] *= sc1; o[nt][3] *= sc1;
            }
            m0 = mn0; m1 = mn1;
            __syncwarp();
            const uint32_t* Vu = (const uint32_t*)Vs;
            #pragma unroll
            for (int ks = 0; ks < 4; ks++) {
                uint32_t ap[4];
                const uint32_t* pb = Pu + (w * 16) * PST + ks * 8;
                ap[0] = pb[g * PST + tg];
                ap[1] = pb[(g + 8) * PST + tg];
                ap[2] = pb[g * PST + tg + 4];
                ap[3] = pb[(g + 8) * PST + tg + 4];
                #pragma unroll
                for (int nt = 0; nt < 8; nt++) {
                    uint32_t bb[2];
                    bb[0] = Vu[(ks * 8 + tg) * VST + nt * 8 + g];
                    bb[1] = Vu[(ks * 8 + tg + 4) * VST + nt * 8 + g];
                    mma8(o[nt], ap, bb);
                }
            }
        }
        __syncthreads();
    }
    #pragma unroll
    for (int ofs = 1; ofs <= 2; ofs <<= 1) {
        l0 += __shfl_xor_sync(0xffffffffu, l0, ofs);
        l1 += __shfl_xor_sync(0xffffffffu, l1, ofs);
    }
    float i0 = 1.f / l0, i1 = 1.f / l1;
    float* o0 = O + base + (size_t)r0 * Dc;
    float* o1 = O + base + (size_t)r1 * Dc;
    #pragma unroll
    for (int nt = 0; nt < 8; nt++) {
        *(float2*)&o0[nt * 8 + 2 * tg] = make_float2(o[nt][0] * i0, o[nt][1] * i0);
        *(float2*)&o1[nt * 8 + 2 * tg] = make_float2(o[nt][2] * i1, o[nt][3] * i1);
    }
}

// ---------------- meta reset (perm + counters only) ----------------
__global__ void zero_meta() {
    int i = blockIdx.x * blockDim.x + threadIdx.x;
    if (i < PERM_MAX) { g_perm[i] = 0; g_wgt[i] = 0.f; }
    if (i < Ec) { g_cnt[i] = 0; g_fill[i] = 0; }
}

// ---------------- router ----------------
__global__ void router_kernel(const float* __restrict__ RW, const float* __restrict__ BIAS) {
    int t = blockIdx.x * 8 + (threadIdx.x >> 5);
    int lane = threadIdx.x & 31;
    const float* x = g_A + (size_t)t * Dc;
    float acc[Ec];
    #pragma unroll
    for (int e = 0; e < Ec; e++) acc[e] = 0.f;
    for (int d = lane; d < Dc; d += 32) {
        float xv = x[d];
        #pragma unroll
        for (int e = 0; e < Ec; e++) acc[e] = fmaf(xv, RW[e * Dc + d], acc[e]);
    }
    #pragma unroll
    for (int e = 0; e < Ec; e++) {
        #pragma unroll
        for (int o = 16; o > 0; o >>= 1) acc[e] += __shfl_xor_sync(0xffffffffu, acc[e], o);
    }
    if (lane == 0) {
        float gg[Ec];
        #pragma unroll
        for (int e = 0; e < Ec; e++) gg[e] = 1.f / (1.f + expf(-(acc[e] + BIAS[e])));
        int i0 = 0; float g0 = gg[0];
        #pragma unroll
        for (int e = 1; e < Ec; e++) if (gg[e] > g0) { g0 = gg[e]; i0 = e; }
        int i1 = -1; float g1 = -1e30f;
        #pragma unroll
        for (int e = 0; e < Ec; e++) if (e != i0 && gg[e] > g1) { g1 = gg[e]; i1 = e; }
        float s = g0 + g1 + 1e-9f;
        g_tok_e[2 * t] = i0;     g_tok_w[2 * t] = g0 / s;
        g_tok_e[2 * t + 1] = i1; g_tok_w[2 * t + 1] = g1 / s;
        atomicAdd(&g_cnt[i0], 1);
        atomicAdd(&g_cnt[i1], 1);
    }
}

__global__ void scan_kernel() {
    int b = 0;
    for (int e = 0; e < Ec; e++) {
        g_pbase[e] = b;
        g_end[e] = b + g_cnt[e];
        b += (g_cnt[e] + 127) & ~127;
    }
    g_pbase[Ec] = b;
    g_total = b;
}

__global__ void fill_kernel() {
    int a = blockIdx.x * blockDim.x + threadIdx.x;
    if (a >= 2 * Tc) return;
    int e = g_tok_e[a];
    float w = g_tok_w[a];
    int pos = atomicAdd(&g_fill[e], 1);
    int r = g_pbase[e] + pos;
    g_perm[r] = a >> 1;
    g_wgt[r] = w;
}

// ---------------- launcher ----------------
extern "C" void kernel_launch(void* const* d_in, const int* in_sizes, int n_in,
                              void* d_out, int out_size) {
    const float* x   = (const float*)d_in[0];
    const float* n1w = (const float*)d_in[1];
    const float* wq  = (const float*)d_in[2];
    const float* wk  = (const float*)d_in[3];
    const float* wv  = (const float*)d_in[4];
    const float* wo  = (const float*)d_in[5];
    const float* n2w = (const float*)d_in[6];
    const float* rw  = (const float*)d_in[7];
    const float* eb  = (const float*)d_in[8];
    const float* sg  = (const float*)d_in[9];
    const float* su  = (const float*)d_in[10];
    const float* sd  = (const float*)d_in[11];
    const float* eg  = (const float*)d_in[12];
    const float* eu  = (const float*)d_in[13];
    const float* ed  = (const float*)d_in[14];
    float* out = (float*)d_out;

    float *pA, *pB, *pC, *pD, *pE, *pF, *pCG;
    cudaGetSymbolAddress((void**)&pA, g_A);
    cudaGetSymbolAddress((void**)&pB, g_B);
    cudaGetSymbolAddress((void**)&pC, g_C);
    cudaGetSymbolAddress((void**)&pD, g_D);
    cudaGetSymbolAddress((void**)&pE, g_E);
    cudaGetSymbolAddress((void**)&pF, g_F);
    cudaGetSymbolAddress((void**)&pCG, g_cg);

    cudaFuncSetAttribute(gemm_mma, cudaFuncAttributeMaxDynamicSharedMemorySize, SMEM_GEMM);
    cudaFuncSetAttribute(gemm_gather_mma, cudaFuncAttributeMaxDynamicSharedMemorySize, SMEM_GEMM);
    cudaFuncSetAttribute(gemm_down_mma, cudaFuncAttributeMaxDynamicSharedMemorySize, SMEM_GEMM);

    dim3 gDen(Dc / 256, Tc / 128);          // (4, 64)
    dim3 gGath(Ic / 256, PERM_MAX / 128);   // (4, 144)
    dim3 gDown(Dc / 256, PERM_MAX / 128);

    // attention branch
    rmsnorm_kernel<<<Tc, 256>>>(x, n1w, pA);
    gemm_mma<<<gDen, 256, SMEM_GEMM>>>(pA, wq, nullptr, pB, Tc, Dc, Dc, 0);
    gemm_mma<<<gDen, 256, SMEM_GEMM>>>(pA, wk, nullptr, pC, Tc, Dc, Dc, 0);
    gemm_mma<<<gDen, 256, SMEM_GEMM>>>(pA, wv, nullptr, pD, Tc, Dc, Dc, 0);
    rope_kernel<<<Tc * Hc / 8, 256>>>(pB, pC);
    attn_mma<<<dim3(Sc / 64, Hc, Bc), 128>>>(pB, pC, pD, pE);
    gemm_mma<<<gDen, 256, SMEM_GEMM>>>(pE, wo, x, pF, Tc, Dc, Dc, 1);   // x1 = ctx.wo^T + x

    // MoE branch
    rmsnorm_kernel<<<Tc, 256>>>(pF, n2w, pA);                            // h2
    gemm_mma<<<gDen, 256, SMEM_GEMM>>>(pA, sg, nullptr, pB, Tc, Ic, Dc, 0);    // gate
    gemm_mma<<<gDen, 256, SMEM_GEMM>>>(pA, su, pB, pB, Tc, Ic, Dc, 2);         // act = silu(g)*up
    gemm_mma<<<gDen, 256, SMEM_GEMM>>>(pB, sd, pF, out, Tc, Dc, Ic, 1);        // out = x1 + shared

    zero_meta<<<(PERM_MAX + 255) / 256, 256>>>();
    router_kernel<<<Tc / 8, 256>>>(rw, eb);
    scan_kernel<<<1, 1>>>();
    fill_kernel<<<(2 * Tc + 255) / 256, 256>>>();
    gemm_gather_mma<<<gGath, 256, SMEM_GEMM>>>(pA, eg, nullptr, pCG, 0);       // routed gate
    gemm_gather_mma<<<gGath, 256, SMEM_GEMM>>>(pA, eu, pCG, pCG, 2);           // act = silu(g)*u
    gemm_down_mma<<<gDown, 256, SMEM_GEMM>>>(pCG, ed, out);                    // out += routed

    (void)in_sizes; (void)n_in; (void)out_size;
}

// round 17
// speedup vs baseline: 1.2116x; 1.1516x over previous
#include <cuda_runtime.h>
#include <math.h>
#include <float.h>
#include <stdint.h>

// ---------------- problem constants ----------------
constexpr int Bc  = 4;
constexpr int Sc  = 2048;
constexpr int Dc  = 1024;
constexpr int Hc  = 16;
constexpr int DHc = 64;
constexpr int Ec  = 16;
constexpr int Ic  = 1024;
constexpr int Tc  = Bc * Sc;                 // 8192 tokens
constexpr int PERM_MAX = 2 * Tc + 128 * Ec;  // 18432, multiple of 128

constexpr int LDSS = 36;                       // smem row stride (u32)
constexpr int SST  = 384 * LDSS;               // u32 per stage (128 A rows + 256 B rows)
constexpr int SMEM_GEMM = 4 * SST * 4;         // 221184 B (4 stages)

// ---------------- scratch (device globals; no allocs allowed) ----------------
__device__ float g_A[Tc * Dc];
__device__ float g_B[Tc * Ic];
__device__ float g_C[Tc * Ic];
__device__ float g_D[Tc * Dc];
__device__ float g_E[Tc * Dc];
__device__ float g_F[Tc * Dc];
__device__ float g_cg[PERM_MAX * Ic];
__device__ float g_cu[PERM_MAX * Ic];

__device__ int   g_cnt[Ec];
__device__ int   g_fill[Ec];
__device__ int   g_pbase[Ec + 1];
__device__ int   g_end[Ec];
__device__ int   g_total;
__device__ int   g_perm[PERM_MAX];
__device__ float g_wgt[PERM_MAX];
__device__ int   g_tok_e[2 * Tc];
__device__ float g_tok_w[2 * Tc];

// ---------------- mma / async helpers ----------------
__device__ __forceinline__ uint32_t f2tf32(float f) {
    uint32_t r;
    asm("cvt.rna.tf32.f32 %0, %1;" : "=r"(r) : "f"(f));
    return r;
}

__device__ __forceinline__ void mma8(float* c, const uint32_t* a, const uint32_t* b) {
    asm volatile(
        "mma.sync.aligned.m16n8k8.row.col.f32.tf32.tf32.f32 "
        "{%0,%1,%2,%3}, {%4,%5,%6,%7}, {%8,%9}, {%0,%1,%2,%3};"
        : "+f"(c[0]), "+f"(c[1]), "+f"(c[2]), "+f"(c[3])
        : "r"(a[0]), "r"(a[1]), "r"(a[2]), "r"(a[3]), "r"(b[0]), "r"(b[1]));
}

__device__ __forceinline__ void ldsm_x4(uint32_t* r, uint32_t addr) {
    asm volatile("ldmatrix.sync.aligned.m8n8.x4.shared.b16 {%0,%1,%2,%3}, [%4];"
        : "=r"(r[0]), "=r"(r[1]), "=r"(r[2]), "=r"(r[3]) : "r"(addr));
}

__device__ __forceinline__ void cp16(uint32_t dst, const void* src) {
    asm volatile("cp.async.cg.shared.global [%0], [%1], 16;" :: "r"(dst), "l"(src));
}
#define CP_COMMIT() asm volatile("cp.async.commit_group;" ::: "memory")
#define CP_WAIT(n)  asm volatile("cp.async.wait_group %0;" :: "n"(n) : "memory")

// compute over one staged ktile: A[128x32] + B[256x32]; warp tile 64x64 via ldmatrix
__device__ __forceinline__ void tile_compute64(uint32_t stage_addr, float c[4][8][4],
                                               int wm, int wn, int lane) {
    const int rowA = ((lane >> 3) & 1) * 8 + (lane & 7);
    const int colA = (lane >> 4) * 4;
    const int rowB = (lane >> 4) * 8 + (lane & 7);
    const int colB = ((lane >> 3) & 1) * 4;
    const uint32_t aBase = stage_addr + (uint32_t)((wm * 64 + rowA) * LDSS + colA) * 4;
    const uint32_t bBase = stage_addr + (uint32_t)((128 + wn * 64 + rowB) * LDSS + colB) * 4;
    #pragma unroll
    for (int ks = 0; ks < 4; ks++) {
        const uint32_t k0 = ks * 8 * 4;
        uint32_t af[4][4], bf[8][2];
        #pragma unroll
        for (int mt = 0; mt < 4; mt++)
            ldsm_x4(af[mt], aBase + (uint32_t)(mt * 16 * LDSS) * 4 + k0);
        #pragma unroll
        for (int np = 0; np < 4; np++) {
            uint32_t r[4];
            ldsm_x4(r, bBase + (uint32_t)(np * 16 * LDSS) * 4 + k0);
            bf[np * 2][0] = r[0]; bf[np * 2][1] = r[1];
            bf[np * 2 + 1][0] = r[2]; bf[np * 2 + 1][1] = r[3];
        }
        #pragma unroll
        for (int mt = 0; mt < 4; mt++)
            #pragma unroll
            for (int nt = 0; nt < 8; nt++)
                mma8(c[mt][nt], af[mt], bf[nt]);
    }
}

// 4-stage cp.async pipeline, one barrier per ktile, 3-ktile lookahead.
__device__ __forceinline__ void pipe_gemm(uint32_t* sm, const float* pa, const float* pb0,
                                          const float* pb1, int tid, int NT,
                                          float c[4][8][4], int wm, int wn, int lane) {
    const uint32_t smaddr = (uint32_t)__cvta_generic_to_shared(sm);
    const uint32_t aoff  = ((uint32_t)((tid >> 1) * LDSS + (tid & 1) * 16)) * 4;
    const uint32_t b0off = aoff + 128u * LDSS * 4;
    const uint32_t b1off = aoff + 256u * LDSS * 4;

    // prologue: stages 0..2
    #pragma unroll
    for (int s = 0; s < 3; s++) {
        uint32_t sb = smaddr + (uint32_t)s * SST * 4;
        #pragma unroll
        for (int i = 0; i < 4; i++) cp16(sb + aoff + i * 16, pa + s * 32 + i * 4);
        #pragma unroll
        for (int i = 0; i < 4; i++) cp16(sb + b0off + i * 16, pb0 + s * 32 + i * 4);
        #pragma unroll
        for (int i = 0; i < 4; i++) cp16(sb + b1off + i * 16, pb1 + s * 32 + i * 4);
        CP_COMMIT();
    }

    int stage = 0;
    for (int kt = 0; kt < NT; kt++) {
        int rem = NT - kt - 1;
        if (rem >= 2) { CP_WAIT(2); } else if (rem == 1) { CP_WAIT(1); } else { CP_WAIT(0); }
        __syncthreads();
        if (kt + 3 < NT) {
            int ns = stage + 3; if (ns >= 4) ns -= 4;
            uint32_t sb = smaddr + (uint32_t)ns * SST * 4;
            const float* qa  = pa  + (kt + 3) * 32;
            const float* qb0 = pb0 + (kt + 3) * 32;
            const float* qb1 = pb1 + (kt + 3) * 32;
            #pragma unroll
            for (int i = 0; i < 4; i++) cp16(sb + aoff + i * 16, qa + i * 4);
            #pragma unroll
            for (int i = 0; i < 4; i++) cp16(sb + b0off + i * 16, qb0 + i * 4);
            #pragma unroll
            for (int i = 0; i < 4; i++) cp16(sb + b1off + i * 16, qb1 + i * 4);
            CP_COMMIT();
        }
        tile_compute64(smaddr + (uint32_t)stage * SST * 4, c, wm, wn, lane);
        if (++stage == 4) stage = 0;
    }
}

// ---------------- RMSNorm ----------------
__global__ void rmsnorm_kernel(const float* __restrict__ X,
                               const float* __restrict__ W,
                               float* __restrict__ Y) {
    int t = blockIdx.x;
    int tid = threadIdx.x;
    const float4* xr = (const float4*)(X + (size_t)t * Dc);
    float4 xv = xr[tid];
    float ss = xv.x * xv.x + xv.y * xv.y + xv.z * xv.z + xv.w * xv.w;

    __shared__ float red[8];
    #pragma unroll
    for (int o = 16; o > 0; o >>= 1) ss += __shfl_xor_sync(0xffffffffu, ss, o);
    if ((tid & 31) == 0) red[tid >> 5] = ss;
    __syncthreads();
    float tot = 0.f;
    if (tid < 8) tot = red[tid];
    #pragma unroll
    for (int o = 4; o > 0; o >>= 1) tot += __shfl_xor_sync(0xffu, tot, o);
    __shared__ float s_inv;
    if (tid == 0) s_inv = rsqrtf(tot / (float)Dc + 1e-6f);
    __syncthreads();
    float inv = s_inv;

    float4 wv = ((const float4*)W)[tid];
    float4 out;
    out.x = xv.x * inv * wv.x;
    out.y = xv.y * inv * wv.y;
    out.z = xv.z * inv * wv.z;
    out.w = xv.w * inv * wv.w;
    ((float4*)(Y + (size_t)t * Dc))[tid] = out;
}

// ---------------- dense tf32 GEMM: C[M,N] = A[M,K].W[N,K]^T (+Res), CTA 128x256 ----------------
__global__ __launch_bounds__(256, 1)
void gemm_mma(const float* __restrict__ A, const float* __restrict__ W,
              const float* __restrict__ Res, float* __restrict__ C,
              int M, int N, int K) {
    extern __shared__ uint32_t sm[];
    const int tid = threadIdx.x, warp = tid >> 5, lane = tid & 31;
    const int wm = warp & 1, wn = warp >> 1;
    const int m0 = blockIdx.y * 128, n0 = blockIdx.x * 256;
    const int hrow = tid >> 1, hcol = (tid & 1) * 16;

    const float* pa  = A + (size_t)(m0 + hrow) * K + hcol;
    const float* pb0 = W + (size_t)(n0 + hrow) * K + hcol;
    const float* pb1 = W + (size_t)(n0 + 128 + hrow) * K + hcol;

    float c[4][8][4];
    #pragma unroll
    for (int a = 0; a < 4; a++)
        #pragma unroll
        for (int b = 0; b < 8; b++)
            #pragma unroll
            for (int d = 0; d < 4; d++) c[a][b][d] = 0.f;

    pipe_gemm(sm, pa, pb0, pb1, tid, K >> 5, c, wm, wn, lane);

    const int g = lane >> 2, tg = lane & 3;
    #pragma unroll
    for (int mt = 0; mt < 4; mt++) {
        #pragma unroll
        for (int nt = 0; nt < 8; nt++) {
            int row = m0 + wm * 64 + mt * 16 + g;
            int col = n0 + wn * 64 + nt * 8 + 2 * tg;
            float2 v0 = make_float2(c[mt][nt][0], c[mt][nt][1]);
            float2 v1 = make_float2(c[mt][nt][2], c[mt][nt][3]);
            if (Res) {
                float2 r0 = *(const float2*)&Res[(size_t)row * N + col];
                float2 r1 = *(const float2*)&Res[(size_t)(row + 8) * N + col];
                v0.x += r0.x; v0.y += r0.y; v1.x += r1.x; v1.y += r1.y;
            }
            *(float2*)&C[(size_t)row * N + col] = v0;
            *(float2*)&C[(size_t)(row + 8) * N + col] = v1;
        }
    }
}

// ---------------- gathered tf32 GEMM ----------------
__global__ __launch_bounds__(256, 1)
void gemm_gather_mma(const float* __restrict__ Xsrc, const float* __restrict__ Wbase,
                     float* __restrict__ Cout) {
    const int m0 = blockIdx.y * 128;
    if (m0 >= g_total) return;
    extern __shared__ uint32_t sm[];
    const int tid = threadIdx.x, warp = tid >> 5, lane = tid & 31;
    const int wm = warp & 1, wn = warp >> 1;
    const int n0 = blockIdx.x * 256;
    int e = 0;
    #pragma unroll
    for (int i = 1; i < Ec; i++) if (g_pbase[i] <= m0) e = i;
    const float* W = Wbase + (size_t)e * Ic * Dc;

    const int hrow = tid >> 1, hcol = (tid & 1) * 16;
    const int tok = g_perm[m0 + hrow];
    const float* pa  = Xsrc + (size_t)tok * Dc + hcol;
    const float* pb0 = W + (size_t)(n0 + hrow) * Dc + hcol;
    const float* pb1 = W + (size_t)(n0 + 128 + hrow) * Dc + hcol;

    float c[4][8][4];
    #pragma unroll
    for (int a = 0; a < 4; a++)
        #pragma unroll
        for (int b = 0; b < 8; b++)
            #pragma unroll
            for (int d = 0; d < 4; d++) c[a][b][d] = 0.f;

    pipe_gemm(sm, pa, pb0, pb1, tid, Dc >> 5, c, wm, wn, lane);

    const int g = lane >> 2, tg = lane & 3;
    #pragma unroll
    for (int mt = 0; mt < 4; mt++) {
        #pragma unroll
        for (int nt = 0; nt < 8; nt++) {
            int row = m0 + wm * 64 + mt * 16 + g;
            int col = n0 + wn * 64 + nt * 8 + 2 * tg;
            *(float2*)&Cout[(size_t)row * Ic + col] = make_float2(c[mt][nt][0], c[mt][nt][1]);
            *(float2*)&Cout[(size_t)(row + 8) * Ic + col] = make_float2(c[mt][nt][2], c[mt][nt][3]);
        }
    }
}

// ---------------- routed down GEMM + weighted atomic scatter (into out) ----------------
__global__ __launch_bounds__(256, 1)
void gemm_down_mma(const float* __restrict__ Act, const float* __restrict__ Wbase,
                   float* __restrict__ Out) {
    const int m0 = blockIdx.y * 128;
    if (m0 >= g_total) return;
    extern __shared__ uint32_t sm[];
    const int tid = threadIdx.x, warp = tid >> 5, lane = tid & 31;
    const int wm = warp & 1, wn = warp >> 1;
    const int n0 = blockIdx.x * 256;
    int e = 0;
    #pragma unroll
    for (int i = 1; i < Ec; i++) if (g_pbase[i] <= m0) e = i;
    const float* W = Wbase + (size_t)e * Dc * Ic;

    const int hrow = tid >> 1, hcol = (tid & 1) * 16;
    const float* pa  = Act + (size_t)(m0 + hrow) * Ic + hcol;
    const float* pb0 = W + (size_t)(n0 + hrow) * Ic + hcol;
    const float* pb1 = W + (size_t)(n0 + 128 + hrow) * Ic + hcol;

    float c[4][8][4];
    #pragma unroll
    for (int a = 0; a < 4; a++)
        #pragma unroll
        for (int b = 0; b < 8; b++)
            #pragma unroll
            for (int d = 0; d < 4; d++) c[a][b][d] = 0.f;

    pipe_gemm(sm, pa, pb0, pb1, tid, Ic >> 5, c, wm, wn, lane);

    const int g = lane >> 2, tg = lane & 3;
    const int eend = g_end[e];
    #pragma unroll
    for (int mt = 0; mt < 4; mt++) {
        int rbase = m0 + wm * 64 + mt * 16 + g;
        #pragma unroll
        for (int half = 0; half < 2; half++) {
            int r = rbase + half * 8;
            if (r < eend) {
                int tok = g_perm[r];
                float wg = g_wgt[r];
                #pragma unroll
                for (int nt = 0; nt < 8; nt++) {
                    int col = n0 + wn * 64 + nt * 8 + 2 * tg;
                    float* Op = Out + (size_t)tok * Dc + col;
                    atomicAdd(&Op[0], wg * c[mt][nt][half * 2 + 0]);
                    atomicAdd(&Op[1], wg * c[mt][nt][half * 2 + 1]);
                }
            }
        }
    }
}

// ---------------- RoPE (in-place on q,k) ----------------
__global__ void rope_kernel(float* __restrict__ Q, float* __restrict__ K) {
    int idx = blockIdx.x * 8 + (threadIdx.x >> 5);
    int lane = threadIdx.x & 31;
    int t = idx / Hc, h = idx % Hc;
    int pos = t & (Sc - 1);
    float inv = expf((float)lane * (-9.210340371976184f / 32.f));
    float ang = (float)pos * inv;
    float sn, cs;
    sincosf(ang, &sn, &cs);
    size_t o = (size_t)t * Dc + h * DHc + lane;
    float q1 = Q[o], q2 = Q[o + 32];
    Q[o]      = q1 * cs - q2 * sn;
    Q[o + 32] = q2 * cs + q1 * sn;
    float k1 = K[o], k2 = K[o + 32];
    K[o]      = k1 * cs - k2 * sn;
    K[o + 32] = k2 * cs + k1 * sn;
}

// ================= mma flash attention =================
constexpr int QST = 68;
constexpr int KST = 68;
constexpr int VST = 72;
constexpr int PST = 36;

__global__ __launch_bounds__(128, 4)
void attn_mma(const float* __restrict__ Q, const float* __restrict__ K,
              const float* __restrict__ V, float* __restrict__ O) {
    const int b = blockIdx.z, h = blockIdx.y, qb = blockIdx.x * 64;
    const int tid = threadIdx.x, w = tid >> 5, lane = tid & 31;
    const int g = lane >> 2, tg = lane & 3;
    __shared__ union { float q[64 * QST]; float p[64 * PST]; } uQ;
    __shared__ float Ks[32 * KST];
    __shared__ float Vs[32 * VST];
    const size_t base = ((size_t)b * Sc) * Dc + (size_t)h * DHc;

    {
        int row = tid >> 1, c0 = (tid & 1) * 32;
        const float* gq = Q + base + (size_t)(qb + row) * Dc + c0;
        #pragma unroll
        for (int i = 0; i < 8; i++)
            *(float4*)&uQ.q[row * QST + c0 + i * 4] = *(const float4*)(gq + i * 4);
    }
    __syncthreads();
    uint32_t aq[8][4];
    #pragma unroll
    for (int ks = 0; ks < 8; ks++) {
        const float* qp = &uQ.q[(w * 16) * QST + ks * 8];
        aq[ks][0] = f2tf32(0.125f * qp[g * QST + tg]);
        aq[ks][1] = f2tf32(0.125f * qp[(g + 8) * QST + tg]);
        aq[ks][2] = f2tf32(0.125f * qp[g * QST + tg + 4]);
        aq[ks][3] = f2tf32(0.125f * qp[(g + 8) * QST + tg + 4]);
    }
    __syncthreads();

    float o[8][4];
    #pragma unroll
    for (int nt = 0; nt < 8; nt++)
        #pragma unroll
        for (int j = 0; j < 4; j++) o[nt][j] = 0.f;
    float m0 = -1e30f, m1 = -1e30f, l0 = 0.f, l1 = 0.f;
    const int r0 = qb + w * 16 + g, r1 = r0 + 8;
    const int qmaxw = qb + w * 16 + 15;
    const int qminw = qb + w * 16;

    for (int t0 = 0; t0 < qb + 64; t0 += 32) {
        {
            int row = tid >> 2, c0 = (tid & 3) * 16;
            const float* gk = K + base + (size_t)(t0 + row) * Dc + c0;
            const float* gv = V + base + (size_t)(t0 + row) * Dc + c0;
            #pragma unroll
            for (int i = 0; i < 4; i++) {
                float4 kv = *(const float4*)(gk + i * 4);
                float4 vv = *(const float4*)(gv + i * 4);
                uint4 ku = make_uint4(f2tf32(kv.x), f2tf32(kv.y), f2tf32(kv.z), f2tf32(kv.w));
                uint4 vu = make_uint4(f2tf32(vv.x), f2tf32(vv.y), f2tf32(vv.z), f2tf32(vv.w));
                *(uint4*)&Ks[row * KST + c0 + i * 4] = ku;
                *(uint4*)&Vs[row * VST + c0 + i * 4] = vu;
            }
        }
        __syncthreads();
        if (t0 <= qmaxw) {
            float s[4][4];
            #pragma unroll
            for (int nt = 0; nt < 4; nt++)
                #pragma unroll
                for (int j = 0; j < 4; j++) s[nt][j] = 0.f;
            const uint32_t* Ku = (const uint32_t*)Ks;
            #pragma unroll
            for (int ks = 0; ks < 8; ks++) {
                #pragma unroll
                for (int nt = 0; nt < 4; nt++) {
                    uint32_t bb[2];
                    bb[0] = Ku[(nt * 8 + g) * KST + ks * 8 + tg];
                    bb[1] = Ku[(nt * 8 + g) * KST + ks * 8 + tg + 4];
                    mma8(s[nt], aq[ks], bb);
                }
            }
            if (t0 + 31 > qminw) {
                #pragma unroll
                for (int nt = 0; nt < 4; nt++) {
                    int k0 = t0 + nt * 8 + 2 * tg;
                    if (k0 > r0)     s[nt][0] = -1e9f;
                    if (k0 + 1 > r0) s[nt][1] = -1e9f;
                    if (k0 > r1)     s[nt][2] = -1e9f;
                    if (k0 + 1 > r1) s[nt][3] = -1e9f;
                }
            }
            float tm0 = fmaxf(fmaxf(s[0][0], s[0][1]), fmaxf(s[1][0], s[1][1]));
            tm0 = fmaxf(tm0, fmaxf(fmaxf(s[2][0], s[2][1]), fmaxf(s[3][0], s[3][1])));
            float tm1 = fmaxf(fmaxf(s[0][2], s[0][3]), fmaxf(s[1][2], s[1][3]));
            tm1 = fmaxf(tm1, fmaxf(fmaxf(s[2][2], s[2][3]), fmaxf(s[3][2], s[3][3])));
            #pragma unroll
            for (int ofs = 1; ofs <= 2; ofs <<= 1) {
                tm0 = fmaxf(tm0, __shfl_xor_sync(0xffffffffu, tm0, ofs));
                tm1 = fmaxf(tm1, __shfl_xor_sync(0xffffffffu, tm1, ofs));
            }
            float mn0 = fmaxf(m0, tm0), mn1 = fmaxf(m1, tm1);
            float sc0 = __expf(m0 - mn0), sc1 = __expf(m1 - mn1);
            float lp0 = 0.f, lp1 = 0.f;
            uint32_t* Pu = (uint32_t*)uQ.p;
            #pragma unroll
            for (int nt = 0; nt < 4; nt++) {
                float p0 = __expf(s[nt][0] - mn0), p1 = __expf(s[nt][1] - mn0);
                float p2 = __expf(s[nt][2] - mn1), p3 = __expf(s[nt][3] - mn1);
                lp0 += p0 + p1; lp1 += p2 + p3;
                *(uint2*)&Pu[(w * 16 + g) * PST + nt * 8 + 2 * tg] =
                    make_uint2(f2tf32(p0), f2tf32(p1));
                *(uint2*)&Pu[(w * 16 + g + 8) * PST + nt * 8 + 2 * tg] =
                    make_uint2(f2tf32(p2), f2tf32(p3));
            }
            l0 = l0 * sc0 + lp0;
            l1 = l1 * sc1 + lp1;
            #pragma unroll
            for (int nt = 0; nt < 8; nt++) {
                o[nt][0] *= sc0; o[nt][1] *= sc0; o[nt][2] *= sc1; o[nt][3] *= sc1;
            }
            m0 = mn0; m1 = mn1;
            __syncwarp();
            const uint32_t* Vu = (const uint32_t*)Vs;
            #pragma unroll
            for (int ks = 0; ks < 4; ks++) {
                uint32_t ap[4];
                const uint32_t* pb = Pu + (w * 16) * PST + ks * 8;
                ap[0] = pb[g * PST + tg];
                ap[1] = pb[(g + 8) * PST + tg];
                ap[2] = pb[g * PST + tg + 4];
                ap[3] = pb[(g + 8) * PST + tg + 4];
                #pragma unroll
                for (int nt = 0; nt < 8; nt++) {
                    uint32_t bb[2];
                    bb[0] = Vu[(ks * 8 + tg) * VST + nt * 8 + g];
                    bb[1] = Vu[(ks * 8 + tg + 4) * VST + nt * 8 + g];
                    mma8(o[nt], ap, bb);
                }
            }
        }
        __syncthreads();
    }
    #pragma unroll
    for (int ofs = 1; ofs <= 2; ofs <<= 1) {
        l0 += __shfl_xor_sync(0xffffffffu, l0, ofs);
        l1 += __shfl_xor_sync(0xffffffffu, l1, ofs);
    }
    float i0 = 1.f / l0, i1 = 1.f / l1;
    float* o0 = O + base + (size_t)r0 * Dc;
    float* o1 = O + base + (size_t)r1 * Dc;
    #pragma unroll
    for (int nt = 0; nt < 8; nt++) {
        *(float2*)&o0[nt * 8 + 2 * tg] = make_float2(o[nt][0] * i0, o[nt][1] * i0);
        *(float2*)&o1[nt * 8 + 2 * tg] = make_float2(o[nt][2] * i1, o[nt][3] * i1);
    }
}

// ---------------- elementwise ----------------
__global__ void silu_mul(float* __restrict__ a, const float* __restrict__ b, long n) {
    long stride = (long)gridDim.x * blockDim.x;
    for (long i = (long)blockIdx.x * blockDim.x + threadIdx.x; i < n; i += stride) {
        float g = a[i];
        a[i] = g / (1.f + __expf(-g)) * b[i];
    }
}

__global__ void silu_mul_compact() {
    long n = (long)g_total * Ic;
    long stride = (long)gridDim.x * blockDim.x;
    for (long i = (long)blockIdx.x * blockDim.x + threadIdx.x; i < n; i += stride) {
        float g = g_cg[i];
        g_cg[i] = g / (1.f + __expf(-g)) * g_cu[i];
    }
}

// ---------------- meta reset (perm + counters only) ----------------
__global__ void zero_meta() {
    int i = blockIdx.x * blockDim.x + threadIdx.x;
    if (i < PERM_MAX) { g_perm[i] = 0; g_wgt[i] = 0.f; }
    if (i < Ec) { g_cnt[i] = 0; g_fill[i] = 0; }
}

// ---------------- router ----------------
__global__ void router_kernel(const float* __restrict__ RW, const float* __restrict__ BIAS) {
    int t = blockIdx.x * 8 + (threadIdx.x >> 5);
    int lane = threadIdx.x & 31;
    const float* x = g_A + (size_t)t * Dc;
    float acc[Ec];
    #pragma unroll
    for (int e = 0; e < Ec; e++) acc[e] = 0.f;
    for (int d = lane; d < Dc; d += 32) {
        float xv = x[d];
        #pragma unroll
        for (int e = 0; e < Ec; e++) acc[e] = fmaf(xv, RW[e * Dc + d], acc[e]);
    }
    #pragma unroll
    for (int e = 0; e < Ec; e++) {
        #pragma unroll
        for (int o = 16; o > 0; o >>= 1) acc[e] += __shfl_xor_sync(0xffffffffu, acc[e], o);
    }
    if (lane == 0) {
        float gg[Ec];
        #pragma unroll
        for (int e = 0; e < Ec; e++) gg[e] = 1.f / (1.f + expf(-(acc[e] + BIAS[e])));
        int i0 = 0; float g0 = gg[0];
        #pragma unroll
        for (int e = 1; e < Ec; e++) if (gg[e] > g0) { g0 = gg[e]; i0 = e; }
        int i1 = -1; float g1 = -1e30f;
        #pragma unroll
        for (int e = 0; e < Ec; e++) if (e != i0 && gg[e] > g1) { g1 = gg[e]; i1 = e; }
        float s = g0 + g1 + 1e-9f;
        g_tok_e[2 * t] = i0;     g_tok_w[2 * t] = g0 / s;
        g_tok_e[2 * t + 1] = i1; g_tok_w[2 * t + 1] = g1 / s;
        atomicAdd(&g_cnt[i0], 1);
        atomicAdd(&g_cnt[i1], 1);
    }
}

__global__ void scan_kernel() {
    int b = 0;
    for (int e = 0; e < Ec; e++) {
        g_pbase[e] = b;
        g_end[e] = b + g_cnt[e];
        b += (g_cnt[e] + 127) & ~127;
    }
    g_pbase[Ec] = b;
    g_total = b;
}

__global__ void fill_kernel() {
    int a = blockIdx.x * blockDim.x + threadIdx.x;
    if (a >= 2 * Tc) return;
    int e = g_tok_e[a];
    float w = g_tok_w[a];
    int pos = atomicAdd(&g_fill[e], 1);
    int r = g_pbase[e] + pos;
    g_perm[r] = a >> 1;
    g_wgt[r] = w;
}

// ---------------- launcher ----------------
extern "C" void kernel_launch(void* const* d_in, const int* in_sizes, int n_in,
                              void* d_out, int out_size) {
    const float* x   = (const float*)d_in[0];
    const float* n1w = (const float*)d_in[1];
    const float* wq  = (const float*)d_in[2];
    const float* wk  = (const float*)d_in[3];
    const float* wv  = (const float*)d_in[4];
    const float* wo  = (const float*)d_in[5];
    const float* n2w = (const float*)d_in[6];
    const float* rw  = (const float*)d_in[7];
    const float* eb  = (const float*)d_in[8];
    const float* sg  = (const float*)d_in[9];
    const float* su  = (const float*)d_in[10];
    const float* sd  = (const float*)d_in[11];
    const float* eg  = (const float*)d_in[12];
    const float* eu  = (const float*)d_in[13];
    const float* ed  = (const float*)d_in[14];
    float* out = (float*)d_out;

    float *pA, *pB, *pC, *pD, *pE, *pF, *pCG, *pCU;
    cudaGetSymbolAddress((void**)&pA, g_A);
    cudaGetSymbolAddress((void**)&pB, g_B);
    cudaGetSymbolAddress((void**)&pC, g_C);
    cudaGetSymbolAddress((void**)&pD, g_D);
    cudaGetSymbolAddress((void**)&pE, g_E);
    cudaGetSymbolAddress((void**)&pF, g_F);
    cudaGetSymbolAddress((void**)&pCG, g_cg);
    cudaGetSymbolAddress((void**)&pCU, g_cu);

    cudaFuncSetAttribute(gemm_mma, cudaFuncAttributeMaxDynamicSharedMemorySize, SMEM_GEMM);
    cudaFuncSetAttribute(gemm_gather_mma, cudaFuncAttributeMaxDynamicSharedMemorySize, SMEM_GEMM);
    cudaFuncSetAttribute(gemm_down_mma, cudaFuncAttributeMaxDynamicSharedMemorySize, SMEM_GEMM);

    dim3 gDen(Dc / 256, Tc / 128);          // (4, 64)
    dim3 gGath(Ic / 256, PERM_MAX / 128);   // (4, 144)
    dim3 gDown(Dc / 256, PERM_MAX / 128);

    // attention branch
    rmsnorm_kernel<<<Tc, 256>>>(x, n1w, pA);
    gemm_mma<<<gDen, 256, SMEM_GEMM>>>(pA, wq, nullptr, pB, Tc, Dc, Dc);
    gemm_mma<<<gDen, 256, SMEM_GEMM>>>(pA, wk, nullptr, pC, Tc, Dc, Dc);
    gemm_mma<<<gDen, 256, SMEM_GEMM>>>(pA, wv, nullptr, pD, Tc, Dc, Dc);
    rope_kernel<<<Tc * Hc / 8, 256>>>(pB, pC);
    attn_mma<<<dim3(Sc / 64, Hc, Bc), 128>>>(pB, pC, pD, pE);
    gemm_mma<<<gDen, 256, SMEM_GEMM>>>(pE, wo, x, pF, Tc, Dc, Dc);   // x1 = ctx.wo^T + x

    // MoE branch (shared expert) — sd GEMM writes out = x1 + shared directly
    rmsnorm_kernel<<<Tc, 256>>>(pF, n2w, pA);                        // h2
    gemm_mma<<<gDen, 256, SMEM_GEMM>>>(pA, sg, nullptr, pB, Tc, Ic, Dc);
    gemm_mma<<<gDen, 256, SMEM_GEMM>>>(pA, su, nullptr, pC, Tc, Ic, Dc);
    silu_mul<<<4096, 256>>>(pB, pC, (long)Tc * Ic);
    gemm_mma<<<gDen, 256, SMEM_GEMM>>>(pB, sd, pF, out, Tc, Dc, Ic); // out = x1 + shared

    // routed experts — down GEMM atomically accumulates into out
    zero_meta<<<(PERM_MAX + 255) / 256, 256>>>();
    router_kernel<<<Tc / 8, 256>>>(rw, eb);
    scan_kernel<<<1, 1>>>();
    fill_kernel<<<(2 * Tc + 255) / 256, 256>>>();
    gemm_gather_mma<<<gGath, 256, SMEM_GEMM>>>(pA, eg, pCG);
    gemm_gather_mma<<<gGath, 256, SMEM_GEMM>>>(pA, eu, pCU);
    silu_mul_compact<<<4096, 256>>>();
    gemm_down_mma<<<gDown, 256, SMEM_GEMM>>>(pCG, ed, out);

    (void)in_sizes; (void)n_in; (void)out_size;
}